// round 14
// baseline (speedup 1.0000x reference)
#include <cuda_runtime.h>

#define D_   128
#define MAXN 50000
#define NBLK_NODE 128

// ---------------- scratch (device globals, zero-init at load) ----------------
__device__ float4 g_nodeacc[MAXN];            // {denom0, denom1, S1_0, S1_1} (self-cleaned)
__device__ float4 g_v[MAXN];                  // {vA0, vA1, vB0, vB1}
__device__ float  g_part[14][NBLK_NODE];      // per-block partial centered moments
__device__ float4 g_A[D_];                    // per-d affine coeffs after BN
__device__ float  g_Ab[D_];
__device__ unsigned int g_ctr;                // last-block-done ticket (self-cleaned)

// packed f32x2 helpers (sm_100+)
#define FMA2(d, a, b, c) \
    asm("fma.rn.f32x2 %0, %1, %2, %3;" : "=l"(d) : "l"(a), "l"(b), "l"(c))
#define ADD2(d, a, b) \
    asm("add.rn.f32x2 %0, %1, %2;" : "=l"(d) : "l"(a), "l"(b))
__device__ __forceinline__ unsigned long long packf2(float lo, float hi) {
    unsigned long long r;
    asm("mov.b64 %0, {%1, %2};" : "=l"(r) : "f"(lo), "f"(hi));
    return r;
}
__device__ __forceinline__ void unpackf2(unsigned long long v, float& lo, float& hi) {
    asm("mov.b64 {%0, %1}, %2;" : "=f"(lo), "=f"(hi) : "l"(v));
}
__device__ __forceinline__ float unpack_sum(unsigned long long v) {
    float lo, hi; unpackf2(v, lo, hi);
    return lo + hi;
}

// ---------------- pass 1: edge logits + exp + scatter (fused, no max pass) ----
// half-warp per edge; lane hl = lane & 15 owns packed dims {hl+32j, hl+32j+16}.
__global__ void __launch_bounds__(256)
k_edge(const int* __restrict__ ei, const float* __restrict__ attr,
       const float* __restrict__ x,
       const float* __restrict__ Wl, const float* __restrict__ Wr,
       const float* __restrict__ We, const float* __restrict__ bl,
       const float* __restrict__ br, const float* __restrict__ att,
       int E) {
    const int hl  = threadIdx.x & 15;
    const int hw  = (blockIdx.x * blockDim.x + threadIdx.x) >> 4;
    const int nhw = (gridDim.x * blockDim.x) >> 4;

    unsigned long long wl2[8], wr2[8], we2[8], bs2[8], at2[8];
#pragma unroll
    for (int j = 0; j < 8; j++) {
        int f0 = hl + 32 * j;
        int f1 = f0 + 16;
        wl2[j] = packf2(Wl[f0], Wl[f1]);
        wr2[j] = packf2(Wr[f0], Wr[f1]);
        we2[j] = packf2(We[f0], We[f1]);
        bs2[j] = packf2(bl[f0] + br[f0], bl[f1] + br[f1]);
        at2[j] = packf2(att[f0], att[f1]);
    }
    // linear-part dots per head: <att,Wl>, <att,Wr>, <att,We>, <att,bs>
    unsigned long long qA0 = 0ull, qB0 = 0ull, qC0 = 0ull, qD0 = 0ull;
    unsigned long long qA1 = 0ull, qB1 = 0ull, qC1 = 0ull, qD1 = 0ull;
#pragma unroll
    for (int j = 0; j < 4; j++) {
        FMA2(qA0, at2[j], wl2[j], qA0); FMA2(qB0, at2[j], wr2[j], qB0);
        FMA2(qC0, at2[j], we2[j], qC0); FMA2(qD0, at2[j], bs2[j], qD0);
        FMA2(qA1, at2[j+4], wl2[j+4], qA1); FMA2(qB1, at2[j+4], wr2[j+4], qB1);
        FMA2(qC1, at2[j+4], we2[j+4], qC1); FMA2(qD1, at2[j+4], bs2[j+4], qD1);
    }
    float pA0 = unpack_sum(qA0), pB0 = unpack_sum(qB0), pC0 = unpack_sum(qC0), pD0 = unpack_sum(qD0);
    float pA1 = unpack_sum(qA1), pB1 = unpack_sum(qB1), pC1 = unpack_sum(qC1), pD1 = unpack_sum(qD1);
#pragma unroll
    for (int o = 8; o > 0; o >>= 1) {
        pA0 += __shfl_xor_sync(~0u, pA0, o); pB0 += __shfl_xor_sync(~0u, pB0, o);
        pC0 += __shfl_xor_sync(~0u, pC0, o); pD0 += __shfl_xor_sync(~0u, pD0, o);
        pA1 += __shfl_xor_sync(~0u, pA1, o); pB1 += __shfl_xor_sync(~0u, pB1, o);
        pC1 += __shfl_xor_sync(~0u, pC1, o); pD1 += __shfl_xor_sync(~0u, pD1, o);
    }

    int e = hw;
    if (e >= E) return;
    int   dst = ei[E + e];
    float c   = attr[e];
    float a   = x[ei[e]];
    float b   = x[dst];

    while (true) {
        // prefetch next edge
        int en = e + nhw;
        int dstn = 0; float cn = 0.f, an = 0.f, bn = 0.f;
        bool has = (en < E);
        if (has) {
            dstn = ei[E + en]; cn = attr[en];
            an = x[ei[en]]; bn = x[dstn];
        }

        unsigned long long a2 = packf2(a, a), b2 = packf2(b, b), c2 = packf2(c, c);
        unsigned long long acc0p = 0ull, acc1p = 0ull;
#pragma unroll
        for (int j = 0; j < 8; j++) {
            unsigned long long t;
            FMA2(t, c2, we2[j], bs2[j]);
            FMA2(t, b2, wr2[j], t);
            FMA2(t, a2, wl2[j], t);
            t &= 0x7FFFFFFF7FFFFFFFull; // packed fabs
            if (j < 4) { FMA2(acc0p, t, at2[j], acc0p); }
            else       { FMA2(acc1p, t, at2[j], acc1p); }
        }
        // pack (acc0, acc1) into one f32x2 and butterfly-reduce packed
        float a0lo, a0hi, a1lo, a1hi;
        unpackf2(acc0p, a0lo, a0hi);
        unpackf2(acc1p, a1lo, a1hi);
        unsigned long long accp = packf2(a0lo + a0hi, a1lo + a1hi);
#pragma unroll
        for (int o = 8; o > 0; o >>= 1) {
            unsigned int lo = (unsigned int)accp, hi = (unsigned int)(accp >> 32);
            lo = __shfl_xor_sync(~0u, lo, o);
            hi = __shfl_xor_sync(~0u, hi, o);
            unsigned long long other = ((unsigned long long)hi << 32) | lo;
            ADD2(accp, accp, other);
        }
        if (hl == 0) {
            float acc0, acc1;
            unpackf2(accp, acc0, acc1);
            float lin0 = fmaf(a, pA0, fmaf(b, pB0, fmaf(c, pC0, pD0)));
            float lin1 = fmaf(a, pA1, fmaf(b, pB1, fmaf(c, pC1, pD1)));
            float a0 = fmaf(0.6f, lin0, 0.4f * acc0);
            float a1 = fmaf(0.6f, lin1, 0.4f * acc1);
            // unnormalized softmax terms (no max subtraction; |alpha| << 88)
            float e0 = __expf(a0);
            float e1 = __expf(a1);
            atomicAdd(&g_nodeacc[dst], make_float4(e0, e1, e0 * a, e1 * a));
        }
        if (!has) break;
        e = en; dst = dstn; c = cn; a = an; b = bn;
    }
}

// ---------------- pass 2: per-node v + moments + BN (last block) ------------
// centered moments of w = (v0, v1, v2-1, v3-1); shift folded into closed form.
// SELF-CLEANING: zeroes g_nodeacc after reading, resets g_ctr, zeroes out[].
__global__ void __launch_bounds__(256)
k_node(int N, int G, double invN, float* __restrict__ out,
       const float* __restrict__ Wl, const float* __restrict__ bl,
       const float* __restrict__ bias, const float* __restrict__ gamma,
       const float* __restrict__ beta) {
    __shared__ float  sm[14][8];
    __shared__ double mom[14];
    __shared__ bool   s_last;
    int tid    = blockIdx.x * blockDim.x + threadIdx.x;
    int stride = gridDim.x * blockDim.x;

    // block 0 zeroes the output accumulator (runs before k_pool's atomics)
    for (int i = tid; i < G * D_; i += stride) out[i] = 0.f;

    float loc[14];
#pragma unroll
    for (int j = 0; j < 14; j++) loc[j] = 0.f;

    const float4 zero4 = make_float4(0.f, 0.f, 0.f, 0.f);
    for (int n = tid; n < N; n += stride) {
        float4 acc = g_nodeacc[n];
        g_nodeacc[n] = zero4;                 // self-clean for next launch
        float i0 = 1.f / (acc.x + 1e-16f);
        float i1 = 1.f / (acc.y + 1e-16f);
        float4 vv = make_float4(acc.z * i0, acc.w * i1, acc.x * i0, acc.y * i1);
        g_v[n] = vv;
        float v0 = vv.x, v1 = vv.y, v2 = vv.z - 1.f, v3 = vv.w - 1.f;
        loc[0] += v0; loc[1] += v1; loc[2] += v2; loc[3] += v3;
        loc[4]  = fmaf(v0, v0, loc[4]);  loc[5]  = fmaf(v0, v1, loc[5]);
        loc[6]  = fmaf(v0, v2, loc[6]);  loc[7]  = fmaf(v0, v3, loc[7]);
        loc[8]  = fmaf(v1, v1, loc[8]);  loc[9]  = fmaf(v1, v2, loc[9]);
        loc[10] = fmaf(v1, v3, loc[10]); loc[11] = fmaf(v2, v2, loc[11]);
        loc[12] = fmaf(v2, v3, loc[12]); loc[13] = fmaf(v3, v3, loc[13]);
    }
#pragma unroll
    for (int j = 0; j < 14; j++) {
#pragma unroll
        for (int o = 16; o > 0; o >>= 1)
            loc[j] += __shfl_xor_sync(~0u, loc[j], o);
    }
    int w = threadIdx.x >> 5, l = threadIdx.x & 31;
    if (l == 0) {
#pragma unroll
        for (int j = 0; j < 14; j++) sm[j][w] = loc[j];
    }
    __syncthreads();
    if (threadIdx.x < 14) {
        float s = 0.f;
#pragma unroll
        for (int k = 0; k < 8; k++) s += sm[threadIdx.x][k];
        g_part[threadIdx.x][blockIdx.x] = s;
    }
    // last-block-done: the final block computes BN coefficients
    __threadfence();
    __syncthreads();
    if (threadIdx.x == 0) {
        unsigned int t = atomicAdd(&g_ctr, 1u);
        s_last = (t == gridDim.x - 1u);
    }
    __syncthreads();
    if (!s_last) return;

    if (threadIdx.x == 0) g_ctr = 0u;        // self-clean ticket

    // reduce 14 moments over NBLK_NODE partials (8 warps, fp64 accumulate)
    for (int m = w; m < 14; m += 8) {
        double s = (double)g_part[m][l] + (double)g_part[m][l + 32]
                 + (double)g_part[m][l + 64] + (double)g_part[m][l + 96];
#pragma unroll
        for (int o = 16; o > 0; o >>= 1)
            s += __shfl_xor_sync(~0u, s, o);
        if (l == 0) mom[m] = s;
    }
    __syncthreads();

    int d = threadIdx.x;
    if (d >= D_) return;
    double mu[4];
#pragma unroll
    for (int k = 0; k < 4; k++) mu[k] = mom[k] * invN;
    double S[4][4];
    const int idx[4][4] = { {4,5,6,7}, {5,8,9,10}, {6,9,11,12}, {7,10,12,13} };
#pragma unroll
    for (int k = 0; k < 4; k++)
#pragma unroll
        for (int j = 0; j < 4; j++) S[k][j] = mom[idx[k][j]] * invN;

    double c[4] = { 0.5 * (double)Wl[d], 0.5 * (double)Wl[128 + d],
                    0.5 * (double)bl[d], 0.5 * (double)bl[128 + d] };
    double c0  = (double)bias[d];
    double c0p = c0 + c[2] + c[3];      // shift: v2,v3 centered at 1
    double lin = 0.0;
#pragma unroll
    for (int k = 0; k < 4; k++) lin += c[k] * mu[k];
    double mean = c0p + lin;
    double quad = 0.0;
#pragma unroll
    for (int k = 0; k < 4; k++)
#pragma unroll
        for (int j = 0; j < 4; j++) quad += c[k] * c[j] * S[k][j];
    double exx = c0p * c0p + 2.0 * c0p * lin + quad;
    double var = exx - mean * mean + 1e-5;
    // s = gamma * rsqrt(var): fp32 seed + 2 fp64 Newton iterations (no DDIV/DSQRT)
    double r = (double)rsqrtf((float)var);
    r = r * (1.5 - 0.5 * var * r * r);
    r = r * (1.5 - 0.5 * var * r * r);
    double s = (double)gamma[d] * r;
    g_A[d]  = make_float4((float)(c[0] * s), (float)(c[1] * s),
                          (float)(c[2] * s), (float)(c[3] * s));
    g_Ab[d] = (float)((c0 - mean) * s + (double)beta[d]);
}

// ---------------- pass 3: evaluate + leaky + segmented pool (pipelined) -----
#define POOL_CHUNK 512
#define SB 8
__global__ void __launch_bounds__(128)
k_pool(const int* __restrict__ batch, float* __restrict__ out, int N) {
    int d  = threadIdx.x;
    int n0 = blockIdx.x * POOL_CHUNK;
    int n1 = n0 + POOL_CHUNK; if (n1 > N) n1 = N;
    if (n0 >= N) return;
    float4 A = g_A[d];
    float Ab = g_Ab[d];
    int curg = batch[n0];
    float acc = 0.f;
    for (int nb = n0; nb < n1; nb += SB) {
        int cnt = n1 - nb; if (cnt > SB) cnt = SB;
        float4 v[SB]; int bg[SB];
#pragma unroll
        for (int i = 0; i < SB; i++) {
            if (i < cnt) { v[i] = g_v[nb + i]; bg[i] = batch[nb + i]; }
        }
#pragma unroll
        for (int i = 0; i < SB; i++) {
            if (i < cnt) {
                float y = fmaf(A.x, v[i].x, fmaf(A.y, v[i].y,
                          fmaf(A.z, v[i].z, fmaf(A.w, v[i].w, Ab))));
                y = fmaxf(y, 0.01f * y);
                if (bg[i] != curg) {
                    atomicAdd(&out[curg * D_ + d], acc);
                    acc = 0.f; curg = bg[i];
                }
                acc += y;
            }
        }
    }
    atomicAdd(&out[curg * D_ + d], acc);
}

// ---------------- launch ----------------
extern "C" void kernel_launch(void* const* d_in, const int* in_sizes, int n_in,
                              void* d_out, int out_size) {
    const float* x     = (const float*)d_in[0];
    const int*   ei    = (const int*)d_in[1];
    const float* attr  = (const float*)d_in[2];
    const int*   batch = (const int*)d_in[3];
    const float* Wl    = (const float*)d_in[4];
    const float* bl    = (const float*)d_in[5];
    const float* Wr    = (const float*)d_in[6];
    const float* br    = (const float*)d_in[7];
    const float* We    = (const float*)d_in[8];
    const float* att   = (const float*)d_in[9];
    const float* bias  = (const float*)d_in[10];
    const float* gamma = (const float*)d_in[11];
    const float* beta  = (const float*)d_in[12];
    float* out = (float*)d_out;

    int N = in_sizes[0];
    int E = in_sizes[2];
    int G = out_size / D_;
    double invN = 1.0 / (double)N;

    k_edge<<<592, 256>>>(ei, attr, x, Wl, Wr, We, bl, br, att, E);
    k_node<<<NBLK_NODE, 256>>>(N, G, invN, out, Wl, bl, bias, gamma, beta);
    k_pool<<<(N + POOL_CHUNK - 1) / POOL_CHUNK, 128>>>(batch, out, N);
}

// round 16
// speedup vs baseline: 1.9529x; 1.9529x over previous
#include <cuda_runtime.h>

#define D_   128
#define MAXN 50000
#define NBLK_NODE 128

// ---------------- scratch (device globals, no allocation) ----------------
__device__ float4 g_nodeacc[MAXN];            // {denom0, denom1, S1_0, S1_1}
__device__ float4 g_v[MAXN];                  // {vA0, vA1, vB0, vB1}
__device__ float  g_part[14][NBLK_NODE];      // per-block partial centered moments
__device__ float4 g_A[D_];                    // per-d affine coeffs after BN
__device__ float  g_Ab[D_];
__device__ unsigned int g_ctr;                // last-block-done ticket

// packed f32x2 helpers (sm_100+)
#define FMA2(d, a, b, c) \
    asm("fma.rn.f32x2 %0, %1, %2, %3;" : "=l"(d) : "l"(a), "l"(b), "l"(c))
#define ADD2(d, a, b) \
    asm("add.rn.f32x2 %0, %1, %2;" : "=l"(d) : "l"(a), "l"(b))
__device__ __forceinline__ unsigned long long packf2(float lo, float hi) {
    unsigned long long r;
    asm("mov.b64 %0, {%1, %2};" : "=l"(r) : "f"(lo), "f"(hi));
    return r;
}
__device__ __forceinline__ void unpackf2(unsigned long long v, float& lo, float& hi) {
    asm("mov.b64 {%0, %1}, %2;" : "=f"(lo), "=f"(hi) : "l"(v));
}
__device__ __forceinline__ float unpack_sum(unsigned long long v) {
    float lo, hi; unpackf2(v, lo, hi);
    return lo + hi;
}

// ---------------- init ----------------
__global__ void k_init(int N, int G, float* out) {
    int i = blockIdx.x * blockDim.x + threadIdx.x;
    if (i < N)      g_nodeacc[i] = make_float4(0.f, 0.f, 0.f, 0.f);
    if (i < G * D_) out[i] = 0.f;
    if (i == 0)     g_ctr = 0u;
}

// ---------------- pass 1: edge logits + exp + scatter, 2 edges/halfwarp/iter -
// half-warp per edge-pair; lane hl = lane & 15 owns packed dims {hl+32j, hl+32j+16}.
__global__ void __launch_bounds__(256, 2)
k_edge(const int* __restrict__ ei, const float* __restrict__ attr,
       const float* __restrict__ x,
       const float* __restrict__ Wl, const float* __restrict__ Wr,
       const float* __restrict__ We, const float* __restrict__ bl,
       const float* __restrict__ br, const float* __restrict__ att,
       int E) {
    const int hl  = threadIdx.x & 15;
    const int hw  = (blockIdx.x * blockDim.x + threadIdx.x) >> 4;
    const int nhw = (gridDim.x * blockDim.x) >> 4;

    unsigned long long wl2[8], wr2[8], we2[8], bs2[8], at2[8];
#pragma unroll
    for (int j = 0; j < 8; j++) {
        int f0 = hl + 32 * j;
        int f1 = f0 + 16;
        wl2[j] = packf2(Wl[f0], Wl[f1]);
        wr2[j] = packf2(Wr[f0], Wr[f1]);
        we2[j] = packf2(We[f0], We[f1]);
        bs2[j] = packf2(bl[f0] + br[f0], bl[f1] + br[f1]);
        at2[j] = packf2(att[f0], att[f1]);
    }
    // linear-part dots per head: <att,Wl>, <att,Wr>, <att,We>, <att,bs>
    unsigned long long qA0 = 0ull, qB0 = 0ull, qC0 = 0ull, qD0 = 0ull;
    unsigned long long qA1 = 0ull, qB1 = 0ull, qC1 = 0ull, qD1 = 0ull;
#pragma unroll
    for (int j = 0; j < 4; j++) {
        FMA2(qA0, at2[j], wl2[j], qA0); FMA2(qB0, at2[j], wr2[j], qB0);
        FMA2(qC0, at2[j], we2[j], qC0); FMA2(qD0, at2[j], bs2[j], qD0);
        FMA2(qA1, at2[j+4], wl2[j+4], qA1); FMA2(qB1, at2[j+4], wr2[j+4], qB1);
        FMA2(qC1, at2[j+4], we2[j+4], qC1); FMA2(qD1, at2[j+4], bs2[j+4], qD1);
    }
    float pA0 = unpack_sum(qA0), pB0 = unpack_sum(qB0), pC0 = unpack_sum(qC0), pD0 = unpack_sum(qD0);
    float pA1 = unpack_sum(qA1), pB1 = unpack_sum(qB1), pC1 = unpack_sum(qC1), pD1 = unpack_sum(qD1);
#pragma unroll
    for (int o = 8; o > 0; o >>= 1) {
        pA0 += __shfl_xor_sync(~0u, pA0, o); pB0 += __shfl_xor_sync(~0u, pB0, o);
        pC0 += __shfl_xor_sync(~0u, pC0, o); pD0 += __shfl_xor_sync(~0u, pD0, o);
        pA1 += __shfl_xor_sync(~0u, pA1, o); pB1 += __shfl_xor_sync(~0u, pB1, o);
        pC1 += __shfl_xor_sync(~0u, pC1, o); pD1 += __shfl_xor_sync(~0u, pD1, o);
    }

    const int stride2 = 2 * nhw;
    int  eA = hw, eB = hw + nhw;
    bool vA = (eA < E), vB = (eB < E);
    if (!vA) return;
    int dA = 0, dB = 0; float cA = 0.f, aA = 0.f, bA = 0.f, cB = 0.f, aB = 0.f, bB = 0.f;
    if (vA) { dA = ei[E + eA]; cA = attr[eA]; aA = x[ei[eA]]; bA = x[dA]; }
    if (vB) { dB = ei[E + eB]; cB = attr[eB]; aB = x[ei[eB]]; bB = x[dB]; }

    while (vA) {
        // prefetch next edge pair
        int enA = eA + stride2, enB = eB + stride2;
        bool wAv = (enA < E), wBv = (enB < E);
        int dnA = 0, dnB = 0; float cnA = 0.f, anA = 0.f, bnA = 0.f, cnB = 0.f, anB = 0.f, bnB = 0.f;
        if (wAv) { dnA = ei[E + enA]; cnA = attr[enA]; anA = x[ei[enA]]; bnA = x[dnA]; }
        if (wBv) { dnB = ei[E + enB]; cnB = attr[enB]; anB = x[ei[enB]]; bnB = x[dnB]; }

        // two independent FMA chains (edges A and B)
        unsigned long long a2A = packf2(aA, aA), b2A = packf2(bA, bA), c2A = packf2(cA, cA);
        unsigned long long a2B = packf2(aB, aB), b2B = packf2(bB, bB), c2B = packf2(cB, cB);
        unsigned long long acc0A = 0ull, acc1A = 0ull, acc0B = 0ull, acc1B = 0ull;
#pragma unroll
        for (int j = 0; j < 8; j++) {
            unsigned long long tA, tB;
            FMA2(tA, c2A, we2[j], bs2[j]);
            FMA2(tB, c2B, we2[j], bs2[j]);
            FMA2(tA, b2A, wr2[j], tA);
            FMA2(tB, b2B, wr2[j], tB);
            FMA2(tA, a2A, wl2[j], tA);
            FMA2(tB, a2B, wl2[j], tB);
            tA &= 0x7FFFFFFF7FFFFFFFull;
            tB &= 0x7FFFFFFF7FFFFFFFull;
            if (j < 4) { FMA2(acc0A, tA, at2[j], acc0A); FMA2(acc0B, tB, at2[j], acc0B); }
            else       { FMA2(acc1A, tA, at2[j], acc1A); FMA2(acc1B, tB, at2[j], acc1B); }
        }
        // pack per-edge (head0, head1) and run two interleaved butterflies
        float lo, hi, lo2, hi2;
        unpackf2(acc0A, lo, hi);  unpackf2(acc1A, lo2, hi2);
        unsigned long long accA = packf2(lo + hi, lo2 + hi2);
        unpackf2(acc0B, lo, hi);  unpackf2(acc1B, lo2, hi2);
        unsigned long long accB = packf2(lo + hi, lo2 + hi2);
#pragma unroll
        for (int o = 8; o > 0; o >>= 1) {
            unsigned int loA = (unsigned int)accA, hiA = (unsigned int)(accA >> 32);
            unsigned int loB = (unsigned int)accB, hiB = (unsigned int)(accB >> 32);
            loA = __shfl_xor_sync(~0u, loA, o); hiA = __shfl_xor_sync(~0u, hiA, o);
            loB = __shfl_xor_sync(~0u, loB, o); hiB = __shfl_xor_sync(~0u, hiB, o);
            unsigned long long oA = ((unsigned long long)hiA << 32) | loA;
            unsigned long long oB = ((unsigned long long)hiB << 32) | loB;
            ADD2(accA, accA, oA);
            ADD2(accB, accB, oB);
        }
        if (hl == 0) {
            float x0, x1;
            unpackf2(accA, x0, x1);
            float lin0 = fmaf(aA, pA0, fmaf(bA, pB0, fmaf(cA, pC0, pD0)));
            float lin1 = fmaf(aA, pA1, fmaf(bA, pB1, fmaf(cA, pC1, pD1)));
            float s0 = __expf(fmaf(0.6f, lin0, 0.4f * x0));
            float s1 = __expf(fmaf(0.6f, lin1, 0.4f * x1));
            atomicAdd(&g_nodeacc[dA], make_float4(s0, s1, s0 * aA, s1 * aA));
            if (vB) {
                unpackf2(accB, x0, x1);
                lin0 = fmaf(aB, pA0, fmaf(bB, pB0, fmaf(cB, pC0, pD0)));
                lin1 = fmaf(aB, pA1, fmaf(bB, pB1, fmaf(cB, pC1, pD1)));
                s0 = __expf(fmaf(0.6f, lin0, 0.4f * x0));
                s1 = __expf(fmaf(0.6f, lin1, 0.4f * x1));
                atomicAdd(&g_nodeacc[dB], make_float4(s0, s1, s0 * aB, s1 * aB));
            }
        }
        vA = wAv; vB = wBv;
        eA = enA; eB = enB;
        dA = dnA; cA = cnA; aA = anA; bA = bnA;
        dB = dnB; cB = cnB; aB = anB; bB = bnB;
    }
}

// ---------------- pass 2: per-node v + moments + BN (last block) ------------
// centered moments of w = (v0, v1, v2-1, v3-1); shift folded into closed form.
__global__ void __launch_bounds__(256)
k_node(int N, double invN,
       const float* __restrict__ Wl, const float* __restrict__ bl,
       const float* __restrict__ bias, const float* __restrict__ gamma,
       const float* __restrict__ beta) {
    __shared__ float  sm[14][8];
    __shared__ double mom[14];
    __shared__ bool   s_last;
    int tid    = blockIdx.x * blockDim.x + threadIdx.x;
    int stride = gridDim.x * blockDim.x;

    float loc[14];
#pragma unroll
    for (int j = 0; j < 14; j++) loc[j] = 0.f;

    for (int n = tid; n < N; n += stride) {
        float4 acc = g_nodeacc[n];
        float i0 = 1.f / (acc.x + 1e-16f);
        float i1 = 1.f / (acc.y + 1e-16f);
        float4 vv = make_float4(acc.z * i0, acc.w * i1, acc.x * i0, acc.y * i1);
        g_v[n] = vv;
        float v0 = vv.x, v1 = vv.y, v2 = vv.z - 1.f, v3 = vv.w - 1.f;
        loc[0] += v0; loc[1] += v1; loc[2] += v2; loc[3] += v3;
        loc[4]  = fmaf(v0, v0, loc[4]);  loc[5]  = fmaf(v0, v1, loc[5]);
        loc[6]  = fmaf(v0, v2, loc[6]);  loc[7]  = fmaf(v0, v3, loc[7]);
        loc[8]  = fmaf(v1, v1, loc[8]);  loc[9]  = fmaf(v1, v2, loc[9]);
        loc[10] = fmaf(v1, v3, loc[10]); loc[11] = fmaf(v2, v2, loc[11]);
        loc[12] = fmaf(v2, v3, loc[12]); loc[13] = fmaf(v3, v3, loc[13]);
    }
#pragma unroll
    for (int j = 0; j < 14; j++) {
#pragma unroll
        for (int o = 16; o > 0; o >>= 1)
            loc[j] += __shfl_xor_sync(~0u, loc[j], o);
    }
    int w = threadIdx.x >> 5, l = threadIdx.x & 31;
    if (l == 0) {
#pragma unroll
        for (int j = 0; j < 14; j++) sm[j][w] = loc[j];
    }
    __syncthreads();
    if (threadIdx.x < 14) {
        float s = 0.f;
#pragma unroll
        for (int k = 0; k < 8; k++) s += sm[threadIdx.x][k];
        g_part[threadIdx.x][blockIdx.x] = s;
    }
    // last-block-done: the final block computes BN coefficients
    __threadfence();
    __syncthreads();
    if (threadIdx.x == 0) {
        unsigned int t = atomicAdd(&g_ctr, 1u);
        s_last = (t == gridDim.x - 1u);
    }
    __syncthreads();
    if (!s_last) return;

    // reduce 14 moments over NBLK_NODE partials (8 warps, fp64 accumulate)
    for (int m = w; m < 14; m += 8) {
        double s = (double)g_part[m][l] + (double)g_part[m][l + 32]
                 + (double)g_part[m][l + 64] + (double)g_part[m][l + 96];
#pragma unroll
        for (int o = 16; o > 0; o >>= 1)
            s += __shfl_xor_sync(~0u, s, o);
        if (l == 0) mom[m] = s;
    }
    __syncthreads();

    int d = threadIdx.x;
    if (d >= D_) return;
    double mu[4];
#pragma unroll
    for (int k = 0; k < 4; k++) mu[k] = mom[k] * invN;
    double S[4][4];
    const int idx[4][4] = { {4,5,6,7}, {5,8,9,10}, {6,9,11,12}, {7,10,12,13} };
#pragma unroll
    for (int k = 0; k < 4; k++)
#pragma unroll
        for (int j = 0; j < 4; j++) S[k][j] = mom[idx[k][j]] * invN;

    double c[4] = { 0.5 * (double)Wl[d], 0.5 * (double)Wl[128 + d],
                    0.5 * (double)bl[d], 0.5 * (double)bl[128 + d] };
    double c0  = (double)bias[d];
    double c0p = c0 + c[2] + c[3];      // shift: v2,v3 centered at 1
    double lin = 0.0;
#pragma unroll
    for (int k = 0; k < 4; k++) lin += c[k] * mu[k];
    double mean = c0p + lin;
    double quad = 0.0;
#pragma unroll
    for (int k = 0; k < 4; k++)
#pragma unroll
        for (int j = 0; j < 4; j++) quad += c[k] * c[j] * S[k][j];
    double exx = c0p * c0p + 2.0 * c0p * lin + quad;
    double var = exx - mean * mean + 1e-5;
    // s = gamma * rsqrt(var): fp32 seed + 2 fp64 Newton iterations (no DDIV/DSQRT)
    double r = (double)rsqrtf((float)var);
    r = r * (1.5 - 0.5 * var * r * r);
    r = r * (1.5 - 0.5 * var * r * r);
    double s = (double)gamma[d] * r;
    g_A[d]  = make_float4((float)(c[0] * s), (float)(c[1] * s),
                          (float)(c[2] * s), (float)(c[3] * s));
    g_Ab[d] = (float)((c0 - mean) * s + (double)beta[d]);
}

// ---------------- pass 3: evaluate + leaky + segmented pool (pipelined) -----
#define POOL_CHUNK 128
#define SB 8
__global__ void __launch_bounds__(128)
k_pool(const int* __restrict__ batch, float* __restrict__ out, int N) {
    int d  = threadIdx.x;
    int n0 = blockIdx.x * POOL_CHUNK;
    int n1 = n0 + POOL_CHUNK; if (n1 > N) n1 = N;
    if (n0 >= N) return;
    float4 A = g_A[d];
    float Ab = g_Ab[d];
    int curg = batch[n0];
    float acc = 0.f;
    for (int nb = n0; nb < n1; nb += SB) {
        int cnt = n1 - nb; if (cnt > SB) cnt = SB;
        float4 v[SB]; int bg[SB];
#pragma unroll
        for (int i = 0; i < SB; i++) {
            if (i < cnt) { v[i] = g_v[nb + i]; bg[i] = batch[nb + i]; }
        }
#pragma unroll
        for (int i = 0; i < SB; i++) {
            if (i < cnt) {
                float y = fmaf(A.x, v[i].x, fmaf(A.y, v[i].y,
                          fmaf(A.z, v[i].z, fmaf(A.w, v[i].w, Ab))));
                y = fmaxf(y, 0.01f * y);
                if (bg[i] != curg) {
                    atomicAdd(&out[curg * D_ + d], acc);
                    acc = 0.f; curg = bg[i];
                }
                acc += y;
            }
        }
    }
    atomicAdd(&out[curg * D_ + d], acc);
}

// ---------------- launch ----------------
extern "C" void kernel_launch(void* const* d_in, const int* in_sizes, int n_in,
                              void* d_out, int out_size) {
    const float* x     = (const float*)d_in[0];
    const int*   ei    = (const int*)d_in[1];
    const float* attr  = (const float*)d_in[2];
    const int*   batch = (const int*)d_in[3];
    const float* Wl    = (const float*)d_in[4];
    const float* bl    = (const float*)d_in[5];
    const float* Wr    = (const float*)d_in[6];
    const float* br    = (const float*)d_in[7];
    const float* We    = (const float*)d_in[8];
    const float* att   = (const float*)d_in[9];
    const float* bias  = (const float*)d_in[10];
    const float* gamma = (const float*)d_in[11];
    const float* beta  = (const float*)d_in[12];
    float* out = (float*)d_out;

    int N = in_sizes[0];
    int E = in_sizes[2];
    int G = out_size / D_;
    double invN = 1.0 / (double)N;

    k_init<<<(N + 255) / 256, 256>>>(N, G, out);
    k_edge<<<592, 256>>>(ei, attr, x, Wl, Wr, We, bl, br, att, E);
    k_node<<<NBLK_NODE, 256>>>(N, invN, Wl, bl, bias, gamma, beta);
    k_pool<<<(N + POOL_CHUNK - 1) / POOL_CHUNK, 128>>>(batch, out, N);
}